// round 15
// baseline (speedup 1.0000x reference)
#include <cuda_runtime.h>
#include <cuda_fp16.h>
#include <cstdint>

// Problem constants
#define B_   4
#define N_   262144          // elements per batch (2^18)
#define F_   64
#define S_   1024            // NUM_SEG
#define OUT_ 64
#define CAP  512             // bin capacity (Poisson lambda=256, >15 sigma headroom)

// ---------------- device scratch ----------------
__device__ __align__(256) unsigned g_zeroblk[2 * B_ * S_ + B_ * 64];
#define CNT_ROW ((int*)g_zeroblk)
#define CNT_COL (((int*)g_zeroblk) + B_ * S_)
#define GSUM    ((float*)(g_zeroblk + 2 * B_ * S_))

__device__ __align__(256) int g_bins[2 * B_ * S_ * CAP];   // 16 MB

__device__ __align__(256) float g_M[4 * F_ * OUT_];        // M_self, M_row, M_col, M_glob
__device__ __align__(256) float g_bias_const[OUT_];
__device__ __align__(256) float g_rowvec[B_ * S_ * OUT_];  // paired: float2[(b,s)][32] = (o, o+32)
__device__ __align__(256) float g_colvec[B_ * S_ * OUT_];

// ---------------- helpers ----------------
__device__ __forceinline__ uint32_t smem_u32(const void* p) {
    uint32_t a;
    asm("{ .reg .u64 t; cvta.to.shared.u64 t, %1; cvt.u32.u64 %0, t; }" : "=r"(a) : "l"(p));
    return a;
}
__device__ __forceinline__ uint32_t f16pk(float lo_e, float hi_e) {   // lower half = lo_e
    const __half2 h = __floats2half2_rn(lo_e, hi_e);
    return *(const uint32_t*)&h;
}
__device__ __forceinline__ void ldsm_x4(uint32_t* r, uint32_t addr) {
    asm volatile("ldmatrix.sync.aligned.m8n8.x4.shared.b16 {%0,%1,%2,%3}, [%4];"
                 : "=r"(r[0]), "=r"(r[1]), "=r"(r[2]), "=r"(r[3]) : "r"(addr));
}
__device__ __forceinline__ void ldsm_x4t(uint32_t* r, uint32_t addr) {
    asm volatile("ldmatrix.sync.aligned.m8n8.x4.trans.shared.b16 {%0,%1,%2,%3}, [%4];"
                 : "=r"(r[0]), "=r"(r[1]), "=r"(r[2]), "=r"(r[3]) : "r"(addr));
}
__device__ __forceinline__ void mma16816(float* c, const uint32_t* a, uint32_t b0, uint32_t b1) {
    asm volatile("mma.sync.aligned.m16n8k16.row.col.f32.f16.f16.f32 "
                 "{%0,%1,%2,%3}, {%4,%5,%6,%7}, {%8,%9}, {%0,%1,%2,%3};"
                 : "+f"(c[0]), "+f"(c[1]), "+f"(c[2]), "+f"(c[3])
                 : "r"(a[0]), "r"(a[1]), "r"(a[2]), "r"(a[3]), "r"(b0), "r"(b1));
}
__device__ __forceinline__ void cp_async16(uint32_t smem_dst, const void* gsrc) {
    asm volatile("cp.async.cg.shared.global [%0], [%1], 16;" :: "r"(smem_dst), "l"(gsrc) : "memory");
}
#define CP_COMMIT() asm volatile("cp.async.commit_group;" ::: "memory")
#define CP_WAIT0()  asm volatile("cp.async.wait_group 0;" ::: "memory")

// ---------------- K0: fold weight matrices ----------------
__global__ void prep_kernel(const float* __restrict__ Wself, const float* __restrict__ Wrow,
                            const float* __restrict__ Wcol,  const float* __restrict__ Wglob,
                            const float* __restrict__ Wout,
                            const float* __restrict__ bself, const float* __restrict__ brow,
                            const float* __restrict__ bcol,  const float* __restrict__ bglob,
                            const float* __restrict__ bout) {
    const int stride = blockDim.x * gridDim.x;
    const int tid = blockIdx.x * blockDim.x + threadIdx.x;
    for (int job = tid; job < 4 * F_ * OUT_; job += stride) {
        const int m = job >> 12;
        const int r = job & 4095;
        const int f = r >> 6, o = r & 63;
        const float* W = (m == 0) ? Wself : (m == 1) ? Wrow : (m == 2) ? Wcol : Wglob;
        float acc = 0.f;
        #pragma unroll 16
        for (int j = 0; j < 64; ++j)
            acc += W[f * 64 + j] * Wout[(m * 64 + j) * OUT_ + o];
        g_M[job] = acc;
    }
    for (int o = tid; o < OUT_; o += stride) {
        float acc = bout[o];
        for (int j = 0; j < 64; ++j) {
            acc += bself[j] * Wout[j * OUT_ + o];
            acc += brow [j] * Wout[(64  + j) * OUT_ + o];
            acc += bcol [j] * Wout[(128 + j) * OUT_ + o];
            acc += bglob[j] * Wout[(192 + j) * OUT_ + o];
        }
        g_bias_const[o] = acc;
    }
}

// ---------------- K1: block-aggregated binning ----------------
__global__ void __launch_bounds__(256) bin_kernel(const int* __restrict__ index) {
    __shared__ int cnt[2048];
    __shared__ int basep[2048];
    const int tid = threadIdx.x;
    const int b = blockIdx.x >> 6;
    const long long ebase = (long long)blockIdx.x * 4096;

    #pragma unroll
    for (int i = 0; i < 8; ++i) cnt[tid + i * 256] = 0;
    __syncthreads();

    int2 p[16];
    int posr[16], posc[16];
    #pragma unroll
    for (int j = 0; j < 16; ++j) {
        p[j] = ((const int2*)index)[ebase + j * 256 + tid];
        posr[j] = atomicAdd(&cnt[p[j].x], 1);
        posc[j] = atomicAdd(&cnt[1024 + p[j].y], 1);
    }
    __syncthreads();

    for (int s = tid; s < 2048; s += 256) {
        const int c = cnt[s];
        if (c > 0) {
            int* ctr = (s < 1024) ? (CNT_ROW + (b << 10) + s)
                                  : (CNT_COL + (b << 10) + (s - 1024));
            basep[s] = atomicAdd(ctr, c);
        }
    }
    __syncthreads();

    #pragma unroll
    for (int j = 0; j < 16; ++j) {
        const int local = (int)((ebase + j * 256 + tid) & (N_ - 1));
        const int sr = basep[p[j].x] + posr[j];
        if (sr < CAP) g_bins[((b << 10) + p[j].x) * CAP + sr] = local;
        const int sc = basep[1024 + p[j].y] + posc[j];
        if (sc < CAP) g_bins[(B_ * S_ + (b << 10) + p[j].y) * CAP + sc] = local;
    }
}

// ---------------- K2: per-segment reduce + fused GEMV (idv-pipelined) ----------------
__global__ void __launch_bounds__(256) reduce_kernel(const float* __restrict__ value) {
    __shared__ float Ms[2 * 4096];
    const int tid = threadIdx.x;
    {
        const float4* src = (const float4*)(g_M + 4096);
        float4* dst = (float4*)Ms;
        #pragma unroll
        for (int i = 0; i < 8; ++i) dst[tid + i * 256] = src[tid + i * 256];
    }
    __syncthreads();

    const int warp = tid >> 5, lane = tid & 31;
    const int job = blockIdx.x * 8 + warp;
    const int side = job >> 12;
    const int bs = job & 4095;
    const int b = bs >> 10;

    const int cnt = (side ? CNT_COL : CNT_ROW)[bs];
    const int mn = min(cnt, CAP);
    const int* ids = g_bins + ((long long)side * B_ * S_ + bs) * CAP;
    const float* vb = value + ((long long)b << 24);

    float2 acc = make_float2(0.f, 0.f);
    int base = 0;
    int idv_next = (mn > 0) ? ids[lane] : 0;   // prefetch first batch's ids
    for (; base + 32 <= mn; base += 32) {
        const int idv = idv_next;
        if (base + 64 <= mn) idv_next = ids[base + 32 + lane];   // prefetch next batch
        #pragma unroll
        for (int jj = 0; jj < 32; jj += 16) {
            float2 v[16];
            #pragma unroll
            for (int j = 0; j < 16; ++j) {
                const int id = __shfl_sync(0xffffffff, idv, jj + j);
                v[j] = *(const float2*)(vb + ((long long)id << 6) + (lane << 1));
            }
            #pragma unroll
            for (int j = 0; j < 16; ++j) { acc.x += v[j].x; acc.y += v[j].y; }
        }
    }
    {
        const int rem = mn - base;
        const int idv = (lane < rem) ? ((base > 0 || mn >= 32) ? ids[base + lane] : idv_next) : 0;
        for (int j = 0; j < rem; ++j) {
            const int id = __shfl_sync(0xffffffff, idv, j);
            const float2 v = *(const float2*)(vb + ((long long)id << 6) + (lane << 1));
            acc.x += v.x; acc.y += v.y;
        }
    }

    if (side == 0) {
        atomicAdd(GSUM + b * 64 + (lane << 1),     acc.x);
        atomicAdd(GSUM + b * 64 + (lane << 1) + 1, acc.y);
    }

    const float inv = 1.0f / ((float)cnt + 1e-9f);
    const float2 mean = make_float2(acc.x * inv, acc.y * inv);

    const float* M = Ms + side * 4096;
    float r0 = 0.f, r1 = 0.f;
    #pragma unroll 8
    for (int j = 0; j < 32; ++j) {
        const float m0 = __shfl_sync(0xffffffff, mean.x, j);
        const float m1 = __shfl_sync(0xffffffff, mean.y, j);
        r0 += m0 * M[(2 * j) * 64 + lane]      + m1 * M[(2 * j + 1) * 64 + lane];
        r1 += m0 * M[(2 * j) * 64 + lane + 32] + m1 * M[(2 * j + 1) * 64 + lane + 32];
    }
    float2* dst = (float2*)((side ? g_colvec : g_rowvec) + ((long long)bs << 6));
    dst[lane] = make_float2(r0, r1);
}

// ---------------- K3: mma.sync main — fp16 GEMM, cp.async staging, 3 CTAs/SM ----------------
// Value tile prefetch moved from 32 registers to cp.async smem staging -> regs ~84,
// occupancy 2 -> 3 CTAs/SM (24 warps). Warp-independent pipelines otherwise as R14:
// wait cp -> convert (own lanes) -> issue cp(g+1) -> ldsm/MMA -> fragment epilogue.
#define SM_A      0                      // fp16 strips: 8 x 2304 B
#define SM_ST     18432                  // float staging: 8 warps x 4096 B
#define SM_B      51200                  // 9216 B (single fp16 image)
#define SM_BB     60416
#define SMEM_MMA  60672
#define ROWS_PER_WARP 128
#define GROUPS 8

__global__ void __launch_bounds__(256, 3) main_mma_kernel(const float* __restrict__ value,
                                                          const int* __restrict__ index,
                                                          float* __restrict__ out) {
    extern __shared__ char sm[];
    const uint32_t smb = smem_u32(sm);
    float* bbF = (float*)(sm + SM_BB);
    const int tid = threadIdx.x;
    const int lane = tid & 31, w = tid >> 5;
    const int b = blockIdx.x >> 8;    // 256 CTAs per batch

    // stage B (single fp16) directly from g_M into padded [k][72] smem rows
    #pragma unroll
    for (int i = 0; i < 8; ++i) {
        const int idx = i * 256 + tid;       // k*32 + p
        const int k = idx >> 5, p = idx & 31;
        const float x0 = g_M[k * 64 + 2 * p];
        const float x1 = g_M[k * 64 + 2 * p + 1];
        *(uint32_t*)(sm + SM_B + k * 144 + p * 4) = f16pk(x0, x1);
    }
    // per-batch bias
    if (tid < 64) {
        const float s = 1.0f / (float)N_;
        float acc = g_bias_const[tid];
        #pragma unroll 8
        for (int f = 0; f < 64; ++f)
            acc += (GSUM[(b << 6) + f] * s) * g_M[3 * 4096 + f * 64 + tid];
        bbF[tid] = acc;
    }
    __syncthreads();   // the ONLY block barrier

    const int c0 = (lane & 3) * 2;
    const float2* rvbase = (const float2*)g_rowvec + ((long long)b << 15);
    const float2* cvbase = (const float2*)g_colvec + ((long long)b << 15);

    // warp-private regions
    const uint32_t aS  = smb + SM_A  + w * 2304;   // fp16 strip (16 rows x 144 B)
    const uint32_t stS = smb + SM_ST + w * 4096;   // float staging (16 rows x 256 B)

    const long long wbase = ((long long)blockIdx.x << 10) + (long long)w * ROWS_PER_WARP;

    // issue group 0 staging + index prefetch
    int2 pp;
    {
        const float* src = value + (wbase << 6);
        #pragma unroll
        for (int i = 0; i < 8; ++i) {
            const int idx = i * 32 + lane;
            cp_async16(stS + idx * 16, src + idx * 4);
        }
        CP_COMMIT();
        if (lane < 16) pp = ((const int2*)index)[wbase + lane];
    }

    for (int g = 0; g < GROUPS; ++g) {
        const long long gbase = wbase + (long long)g * 16;

        CP_WAIT0();   // staging ready (each lane converts exactly the data it staged)

        // convert staged floats to fp16 in this warp's strip
        #pragma unroll
        for (int i = 0; i < 8; ++i) {
            const int idx = i * 32 + lane;       // float4 index: r*16 + q
            const int r = idx >> 4, q = idx & 15;
            const float4 vv = *(const float4*)(sm + SM_ST + w * 4096 + idx * 16);
            const uint32_t h01 = f16pk(vv.x, vv.y);
            const uint32_t h23 = f16pk(vv.z, vv.w);
            *(uint2*)(sm + SM_A + w * 2304 + r * 144 + q * 8) = make_uint2(h01, h23);
        }
        __syncwarp();   // strip visible warp-wide; staging reads complete

        const int2 ppc = pp;   // current group's indices (lanes 0-15)

        // issue next group's staging (flies during MMA + epilogue)
        if (g + 1 < GROUPS) {
            const float* src = value + ((gbase + 16) << 6);
            #pragma unroll
            for (int i = 0; i < 8; ++i) {
                const int idx = i * 32 + lane;
                cp_async16(stS + idx * 16, src + idx * 4);
            }
            CP_COMMIT();
            if (lane < 16) pp = ((const int2*)index)[gbase + 16 + lane];
        }

        float acc[8][4];
        #pragma unroll
        for (int n = 0; n < 8; ++n)
            #pragma unroll
            for (int q = 0; q < 4; ++q) acc[n][q] = 0.f;

        #pragma unroll
        for (int ks = 0; ks < 4; ++ks) {
            uint32_t ah[4];
            const uint32_t aoff = (uint32_t)((lane & 15) * 144 +
                                             (ks * 16 + (lane >> 4) * 8) * 2);
            ldsm_x4(ah, aS + aoff);
            const uint32_t brow = (uint32_t)((ks * 16 + (lane & 15)) * 144 +
                                             ((lane >> 4) * 8) * 2);
            #pragma unroll
            for (int gg = 0; gg < 4; ++gg) {
                uint32_t bh[4];
                ldsm_x4t(bh, smb + SM_B + brow + gg * 32);
                mma16816(acc[2 * gg],     ah, bh[0], bh[1]);
                mma16816(acc[2 * gg + 1], ah, bh[2], bh[3]);
            }
        }

        // fragment-direct epilogue: thread owns rows (lane/4, lane/4+8),
        // cols c0+8j (+1, +32, +33); indices via shfl from lanes 0-15.
        #pragma unroll
        for (int half = 0; half < 2; ++half) {
            const int rg = (lane >> 2) + half * 8;
            const int s = half * 2;
            const int i0 = __shfl_sync(0xffffffff, ppc.x, rg);
            const int i1 = __shfl_sync(0xffffffff, ppc.y, rg);
            const float2* rv = rvbase + ((long long)i0 << 5);
            const float2* cv = cvbase + ((long long)i1 << 5);
            float* op = out + ((gbase + rg) << 6);
            #pragma unroll
            for (int j = 0; j < 4; ++j) {
                const int c = c0 + 8 * j;
                const float2 rv0 = rv[c], rv1 = rv[c + 1];
                const float2 cv0 = cv[c], cv1 = cv[c + 1];
                float x0 = acc[j][s]     + rv0.x + cv0.x + bbF[c];
                float x1 = acc[j][s + 1] + rv1.x + cv1.x + bbF[c + 1];
                float y0 = acc[j + 4][s]     + rv0.y + cv0.y + bbF[c + 32];
                float y1 = acc[j + 4][s + 1] + rv1.y + cv1.y + bbF[c + 33];
                x0 = fmaxf(x0, 0.01f * x0);
                x1 = fmaxf(x1, 0.01f * x1);
                y0 = fmaxf(y0, 0.01f * y0);
                y1 = fmaxf(y1, 0.01f * y1);
                *(float2*)(op + c)      = make_float2(x0, x1);
                *(float2*)(op + c + 32) = make_float2(y0, y1);
            }
        }
        __syncwarp();   // strip reuse safe for next group
    }
}

// ---------------- index pass-through ----------------
__global__ void idxcopy_kernel(const int* __restrict__ idx, float* __restrict__ out, int n4) {
    const int i = blockIdx.x * blockDim.x + threadIdx.x;
    if (i < n4) {
        const int4 v = ((const int4*)idx)[i];
        ((float4*)out)[i] = make_float4((float)v.x, (float)v.y, (float)v.z, (float)v.w);
    }
}

// ---------------- launch ----------------
extern "C" void kernel_launch(void* const* d_in, const int* in_sizes, int n_in,
                              void* d_out, int out_size) {
    const int*   index = (const int*)d_in[0];
    const float* value = (const float*)d_in[1];
    const float* Wself = (const float*)d_in[2];
    const float* bself = (const float*)d_in[3];
    const float* Wrow  = (const float*)d_in[4];
    const float* brow  = (const float*)d_in[5];
    const float* Wcol  = (const float*)d_in[6];
    const float* bcol  = (const float*)d_in[7];
    const float* Wglob = (const float*)d_in[8];
    const float* bglob = (const float*)d_in[9];
    const float* Wout  = (const float*)d_in[10];
    const float* bout  = (const float*)d_in[11];
    float* out = (float*)d_out;

    const long long main_elems = (long long)B_ * N_ * OUT_;
    const long long off = (long long)out_size - main_elems;
    float* out_main = (off > 0) ? (out + off) : out;

    void* zp = nullptr;
    cudaGetSymbolAddress(&zp, g_zeroblk);
    cudaMemsetAsync(zp, 0, sizeof(g_zeroblk), 0);

    cudaFuncSetAttribute(main_mma_kernel, cudaFuncAttributeMaxDynamicSharedMemorySize, SMEM_MMA);

    prep_kernel<<<64, 256>>>(Wself, Wrow, Wcol, Wglob, Wout,
                             bself, brow, bcol, bglob, bout);                     // k1
    bin_kernel<<<(B_ * N_) / 4096, 256>>>(index);                                 // k2
    reduce_kernel<<<1024, 256>>>(value);                                          // k3
    main_mma_kernel<<<1024, 256, SMEM_MMA>>>(value, index, out_main);             // k4 (profiled)
    if (off > 0) {
        const int n4 = (int)(off / 4);
        idxcopy_kernel<<<(n4 + 255) / 256, 256>>>(index, out, n4);                // k5
    }
}

// round 16
// speedup vs baseline: 1.0534x; 1.0534x over previous
#include <cuda_runtime.h>
#include <cuda_fp16.h>
#include <cstdint>

// Problem constants
#define B_   4
#define N_   262144          // elements per batch (2^18)
#define F_   64
#define S_   1024            // NUM_SEG
#define OUT_ 64
#define CAP  512             // bin capacity (Poisson lambda=256, >15 sigma headroom)

// ---------------- device scratch ----------------
__device__ __align__(256) unsigned g_zeroblk[2 * B_ * S_ + B_ * 64];
#define CNT_ROW ((int*)g_zeroblk)
#define CNT_COL (((int*)g_zeroblk) + B_ * S_)
#define GSUM    ((float*)(g_zeroblk + 2 * B_ * S_))

__device__ __align__(256) int g_bins[2 * B_ * S_ * CAP];   // 16 MB

__device__ __align__(256) float g_M[4 * F_ * OUT_];        // M_self, M_row, M_col, M_glob
__device__ __align__(256) float g_bias_const[OUT_];
// fp16 paired tables: uint32[(b,s)][32], each = half2(out o, out o+32)
__device__ __align__(256) uint32_t g_rowvec[B_ * S_ * 32];
__device__ __align__(256) uint32_t g_colvec[B_ * S_ * 32];

// ---------------- helpers ----------------
__device__ __forceinline__ uint32_t smem_u32(const void* p) {
    uint32_t a;
    asm("{ .reg .u64 t; cvta.to.shared.u64 t, %1; cvt.u32.u64 %0, t; }" : "=r"(a) : "l"(p));
    return a;
}
__device__ __forceinline__ uint32_t f16pk(float lo_e, float hi_e) {   // lower half = lo_e
    const __half2 h = __floats2half2_rn(lo_e, hi_e);
    return *(const uint32_t*)&h;
}
__device__ __forceinline__ float2 f16up(uint32_t v) {
    const __half2 h = *(const __half2*)&v;
    return __half22float2(h);
}
__device__ __forceinline__ void ldsm_x4(uint32_t* r, uint32_t addr) {
    asm volatile("ldmatrix.sync.aligned.m8n8.x4.shared.b16 {%0,%1,%2,%3}, [%4];"
                 : "=r"(r[0]), "=r"(r[1]), "=r"(r[2]), "=r"(r[3]) : "r"(addr));
}
__device__ __forceinline__ void ldsm_x4t(uint32_t* r, uint32_t addr) {
    asm volatile("ldmatrix.sync.aligned.m8n8.x4.trans.shared.b16 {%0,%1,%2,%3}, [%4];"
                 : "=r"(r[0]), "=r"(r[1]), "=r"(r[2]), "=r"(r[3]) : "r"(addr));
}
__device__ __forceinline__ void mma16816(float* c, const uint32_t* a, uint32_t b0, uint32_t b1) {
    asm volatile("mma.sync.aligned.m16n8k16.row.col.f32.f16.f16.f32 "
                 "{%0,%1,%2,%3}, {%4,%5,%6,%7}, {%8,%9}, {%0,%1,%2,%3};"
                 : "+f"(c[0]), "+f"(c[1]), "+f"(c[2]), "+f"(c[3])
                 : "r"(a[0]), "r"(a[1]), "r"(a[2]), "r"(a[3]), "r"(b0), "r"(b1));
}

// ---------------- K0: fold weight matrices ----------------
__global__ void prep_kernel(const float* __restrict__ Wself, const float* __restrict__ Wrow,
                            const float* __restrict__ Wcol,  const float* __restrict__ Wglob,
                            const float* __restrict__ Wout,
                            const float* __restrict__ bself, const float* __restrict__ brow,
                            const float* __restrict__ bcol,  const float* __restrict__ bglob,
                            const float* __restrict__ bout) {
    const int stride = blockDim.x * gridDim.x;
    const int tid = blockIdx.x * blockDim.x + threadIdx.x;
    for (int job = tid; job < 4 * F_ * OUT_; job += stride) {
        const int m = job >> 12;
        const int r = job & 4095;
        const int f = r >> 6, o = r & 63;
        const float* W = (m == 0) ? Wself : (m == 1) ? Wrow : (m == 2) ? Wcol : Wglob;
        float acc = 0.f;
        #pragma unroll 16
        for (int j = 0; j < 64; ++j)
            acc += W[f * 64 + j] * Wout[(m * 64 + j) * OUT_ + o];
        g_M[job] = acc;
    }
    for (int o = tid; o < OUT_; o += stride) {
        float acc = bout[o];
        for (int j = 0; j < 64; ++j) {
            acc += bself[j] * Wout[j * OUT_ + o];
            acc += brow [j] * Wout[(64  + j) * OUT_ + o];
            acc += bcol [j] * Wout[(128 + j) * OUT_ + o];
            acc += bglob[j] * Wout[(192 + j) * OUT_ + o];
        }
        g_bias_const[o] = acc;
    }
}

// ---------------- K1: block-aggregated binning ----------------
__global__ void __launch_bounds__(256) bin_kernel(const int* __restrict__ index) {
    __shared__ int cnt[2048];
    __shared__ int basep[2048];
    const int tid = threadIdx.x;
    const int b = blockIdx.x >> 6;
    const long long ebase = (long long)blockIdx.x * 4096;

    #pragma unroll
    for (int i = 0; i < 8; ++i) cnt[tid + i * 256] = 0;
    __syncthreads();

    int2 p[16];
    int posr[16], posc[16];
    #pragma unroll
    for (int j = 0; j < 16; ++j) {
        p[j] = ((const int2*)index)[ebase + j * 256 + tid];
        posr[j] = atomicAdd(&cnt[p[j].x], 1);
        posc[j] = atomicAdd(&cnt[1024 + p[j].y], 1);
    }
    __syncthreads();

    for (int s = tid; s < 2048; s += 256) {
        const int c = cnt[s];
        if (c > 0) {
            int* ctr = (s < 1024) ? (CNT_ROW + (b << 10) + s)
                                  : (CNT_COL + (b << 10) + (s - 1024));
            basep[s] = atomicAdd(ctr, c);
        }
    }
    __syncthreads();

    #pragma unroll
    for (int j = 0; j < 16; ++j) {
        const int local = (int)((ebase + j * 256 + tid) & (N_ - 1));
        const int sr = basep[p[j].x] + posr[j];
        if (sr < CAP) g_bins[((b << 10) + p[j].x) * CAP + sr] = local;
        const int sc = basep[1024 + p[j].y] + posc[j];
        if (sc < CAP) g_bins[(B_ * S_ + (b << 10) + p[j].y) * CAP + sc] = local;
    }
}

// ---------------- K2: per-segment reduce + fused GEMV (idv-pipelined, fp16 table out) ----------------
__global__ void __launch_bounds__(256) reduce_kernel(const float* __restrict__ value) {
    __shared__ float Ms[2 * 4096];
    const int tid = threadIdx.x;
    {
        const float4* src = (const float4*)(g_M + 4096);
        float4* dst = (float4*)Ms;
        #pragma unroll
        for (int i = 0; i < 8; ++i) dst[tid + i * 256] = src[tid + i * 256];
    }
    __syncthreads();

    const int warp = tid >> 5, lane = tid & 31;
    const int job = blockIdx.x * 8 + warp;
    const int side = job >> 12;
    const int bs = job & 4095;
    const int b = bs >> 10;

    const int cnt = (side ? CNT_COL : CNT_ROW)[bs];
    const int mn = min(cnt, CAP);
    const int* ids = g_bins + ((long long)side * B_ * S_ + bs) * CAP;
    const float* vb = value + ((long long)b << 24);

    float2 acc = make_float2(0.f, 0.f);
    int base = 0;
    int idv_next = (mn > 0) ? ids[lane] : 0;   // prefetch first batch's ids
    for (; base + 32 <= mn; base += 32) {
        const int idv = idv_next;
        if (base + 64 <= mn) idv_next = ids[base + 32 + lane];   // prefetch next batch
        #pragma unroll
        for (int jj = 0; jj < 32; jj += 16) {
            float2 v[16];
            #pragma unroll
            for (int j = 0; j < 16; ++j) {
                const int id = __shfl_sync(0xffffffff, idv, jj + j);
                v[j] = *(const float2*)(vb + ((long long)id << 6) + (lane << 1));
            }
            #pragma unroll
            for (int j = 0; j < 16; ++j) { acc.x += v[j].x; acc.y += v[j].y; }
        }
    }
    {
        const int rem = mn - base;
        const int idv = (lane < rem) ? ((base > 0 || mn >= 32) ? ids[base + lane] : idv_next) : 0;
        for (int j = 0; j < rem; ++j) {
            const int id = __shfl_sync(0xffffffff, idv, j);
            const float2 v = *(const float2*)(vb + ((long long)id << 6) + (lane << 1));
            acc.x += v.x; acc.y += v.y;
        }
    }

    if (side == 0) {
        atomicAdd(GSUM + b * 64 + (lane << 1),     acc.x);
        atomicAdd(GSUM + b * 64 + (lane << 1) + 1, acc.y);
    }

    const float inv = 1.0f / ((float)cnt + 1e-9f);
    const float2 mean = make_float2(acc.x * inv, acc.y * inv);

    const float* M = Ms + side * 4096;
    float r0 = 0.f, r1 = 0.f;
    #pragma unroll 8
    for (int j = 0; j < 32; ++j) {
        const float m0 = __shfl_sync(0xffffffff, mean.x, j);
        const float m1 = __shfl_sync(0xffffffff, mean.y, j);
        r0 += m0 * M[(2 * j) * 64 + lane]      + m1 * M[(2 * j + 1) * 64 + lane];
        r1 += m0 * M[(2 * j) * 64 + lane + 32] + m1 * M[(2 * j + 1) * 64 + lane + 32];
    }
    // fp16 paired table: half2(out lane, out lane+32)
    (side ? g_colvec : g_rowvec)[((long long)bs << 5) + lane] = f16pk(r0, r1);
}

// ---------------- K3: mma.sync main — fp16 GEMM, R14 structure, fp16 table gathers ----------------
// Register prefetch (2 CTAs/SM), warp-independent pipelines, fragment-direct epilogue.
// rv/cv gathers now 8B uint2 per table per (row, j) — half the R14 gather traffic.
#define SM_A      0                      // 8 strips x 2304 B
#define SM_B      18432                  // 9216 B (single fp16 image)
#define SM_BB     27648
#define SMEM_MMA  27904
#define ROWS_PER_WARP 128
#define GROUPS 8

__global__ void __launch_bounds__(256, 2) main_mma_kernel(const float* __restrict__ value,
                                                          const int* __restrict__ index,
                                                          float* __restrict__ out) {
    extern __shared__ char sm[];
    const uint32_t smb = smem_u32(sm);
    float* bbF = (float*)(sm + SM_BB);
    const int tid = threadIdx.x;
    const int lane = tid & 31, w = tid >> 5;
    const int b = blockIdx.x >> 8;    // 256 CTAs per batch

    // stage B (single fp16) directly from g_M into padded [k][72] smem rows
    #pragma unroll
    for (int i = 0; i < 8; ++i) {
        const int idx = i * 256 + tid;       // k*32 + p
        const int k = idx >> 5, p = idx & 31;
        const float x0 = g_M[k * 64 + 2 * p];
        const float x1 = g_M[k * 64 + 2 * p + 1];
        *(uint32_t*)(sm + SM_B + k * 144 + p * 4) = f16pk(x0, x1);
    }
    // per-batch bias
    if (tid < 64) {
        const float s = 1.0f / (float)N_;
        float acc = g_bias_const[tid];
        #pragma unroll 8
        for (int f = 0; f < 64; ++f)
            acc += (GSUM[(b << 6) + f] * s) * g_M[3 * 4096 + f * 64 + tid];
        bbF[tid] = acc;
    }
    __syncthreads();   // the ONLY block barrier

    const int c0 = (lane & 3) * 2;
    const uint32_t* rvbase = g_rowvec + ((long long)b << 15);
    const uint32_t* cvbase = g_colvec + ((long long)b << 15);

    // warp-private A strip (16 rows x 144 B)
    const uint32_t aS = smb + SM_A + w * 2304;

    const long long wbase = ((long long)blockIdx.x << 10) + (long long)w * ROWS_PER_WARP;

    // preload group 0
    float4 v[8];
    int2 pp;
    {
        const float4* Vg = (const float4*)(value + (wbase << 6));
        #pragma unroll
        for (int i = 0; i < 8; ++i) v[i] = Vg[i * 32 + lane];
        if (lane < 16) pp = ((const int2*)index)[wbase + lane];
    }

    for (int g = 0; g < GROUPS; ++g) {
        const long long gbase = wbase + (long long)g * 16;

        // convert staged group to fp16 in this warp's strip
        #pragma unroll
        for (int i = 0; i < 8; ++i) {
            const int idx = i * 32 + lane;       // float4 index: r*16 + q
            const int r = idx >> 4, q = idx & 15;
            const uint32_t h01 = f16pk(v[i].x, v[i].y);
            const uint32_t h23 = f16pk(v[i].z, v[i].w);
            *(uint2*)(sm + SM_A + w * 2304 + r * 144 + q * 8) = make_uint2(h01, h23);
        }
        __syncwarp();

        const int2 ppc = pp;   // current group's indices (lanes 0-15)

        // prefetch next group
        if (g + 1 < GROUPS) {
            const float4* Vg = (const float4*)(value + ((gbase + 16) << 6));
            #pragma unroll
            for (int i = 0; i < 8; ++i) v[i] = Vg[i * 32 + lane];
            if (lane < 16) pp = ((const int2*)index)[gbase + 16 + lane];
        }

        float acc[8][4];
        #pragma unroll
        for (int n = 0; n < 8; ++n)
            #pragma unroll
            for (int q = 0; q < 4; ++q) acc[n][q] = 0.f;

        #pragma unroll
        for (int ks = 0; ks < 4; ++ks) {
            uint32_t ah[4];
            const uint32_t aoff = (uint32_t)((lane & 15) * 144 +
                                             (ks * 16 + (lane >> 4) * 8) * 2);
            ldsm_x4(ah, aS + aoff);
            const uint32_t brow = (uint32_t)((ks * 16 + (lane & 15)) * 144 +
                                             ((lane >> 4) * 8) * 2);
            #pragma unroll
            for (int gg = 0; gg < 4; ++gg) {
                uint32_t bh[4];
                ldsm_x4t(bh, smb + SM_B + brow + gg * 32);
                mma16816(acc[2 * gg],     ah, bh[0], bh[1]);
                mma16816(acc[2 * gg + 1], ah, bh[2], bh[3]);
            }
        }

        // fragment-direct epilogue: thread owns rows (lane/4, lane/4+8),
        // cols c0+8j (+1, +32, +33); rv/cv read as 8B uint2 of half2 pairs.
        #pragma unroll
        for (int half = 0; half < 2; ++half) {
            const int rg = (lane >> 2) + half * 8;
            const int s = half * 2;
            const int i0 = __shfl_sync(0xffffffff, ppc.x, rg);
            const int i1 = __shfl_sync(0xffffffff, ppc.y, rg);
            const uint32_t* rv = rvbase + ((long long)i0 << 5);
            const uint32_t* cv = cvbase + ((long long)i1 << 5);
            float* op = out + ((gbase + rg) << 6);
            #pragma unroll
            for (int j = 0; j < 4; ++j) {
                const int c = c0 + 8 * j;
                const uint2 rvu = *(const uint2*)(rv + c);
                const uint2 cvu = *(const uint2*)(cv + c);
                const float2 rv0 = f16up(rvu.x), rv1 = f16up(rvu.y);
                const float2 cv0 = f16up(cvu.x), cv1 = f16up(cvu.y);
                float x0 = acc[j][s]     + rv0.x + cv0.x + bbF[c];
                float x1 = acc[j][s + 1] + rv1.x + cv1.x + bbF[c + 1];
                float y0 = acc[j + 4][s]     + rv0.y + cv0.y + bbF[c + 32];
                float y1 = acc[j + 4][s + 1] + rv1.y + cv1.y + bbF[c + 33];
                x0 = fmaxf(x0, 0.01f * x0);
                x1 = fmaxf(x1, 0.01f * x1);
                y0 = fmaxf(y0, 0.01f * y0);
                y1 = fmaxf(y1, 0.01f * y1);
                *(float2*)(op + c)      = make_float2(x0, x1);
                *(float2*)(op + c + 32) = make_float2(y0, y1);
            }
        }
        __syncwarp();   // strip reuse safe for next group
    }
}

// ---------------- index pass-through ----------------
__global__ void idxcopy_kernel(const int* __restrict__ idx, float* __restrict__ out, int n4) {
    const int i = blockIdx.x * blockDim.x + threadIdx.x;
    if (i < n4) {
        const int4 v = ((const int4*)idx)[i];
        ((float4*)out)[i] = make_float4((float)v.x, (float)v.y, (float)v.z, (float)v.w);
    }
}

// ---------------- launch ----------------
extern "C" void kernel_launch(void* const* d_in, const int* in_sizes, int n_in,
                              void* d_out, int out_size) {
    const int*   index = (const int*)d_in[0];
    const float* value = (const float*)d_in[1];
    const float* Wself = (const float*)d_in[2];
    const float* bself = (const float*)d_in[3];
    const float* Wrow  = (const float*)d_in[4];
    const float* brow  = (const float*)d_in[5];
    const float* Wcol  = (const float*)d_in[6];
    const float* bcol  = (const float*)d_in[7];
    const float* Wglob = (const float*)d_in[8];
    const float* bglob = (const float*)d_in[9];
    const float* Wout  = (const float*)d_in[10];
    const float* bout  = (const float*)d_in[11];
    float* out = (float*)d_out;

    const long long main_elems = (long long)B_ * N_ * OUT_;
    const long long off = (long long)out_size - main_elems;
    float* out_main = (off > 0) ? (out + off) : out;

    void* zp = nullptr;
    cudaGetSymbolAddress(&zp, g_zeroblk);
    cudaMemsetAsync(zp, 0, sizeof(g_zeroblk), 0);

    cudaFuncSetAttribute(main_mma_kernel, cudaFuncAttributeMaxDynamicSharedMemorySize, SMEM_MMA);

    prep_kernel<<<64, 256>>>(Wself, Wrow, Wcol, Wglob, Wout,
                             bself, brow, bcol, bglob, bout);                     // k1
    bin_kernel<<<(B_ * N_) / 4096, 256>>>(index);                                 // k2
    reduce_kernel<<<1024, 256>>>(value);                                          // k3
    main_mma_kernel<<<1024, 256, SMEM_MMA>>>(value, index, out_main);             // k4 (profiled)
    if (off > 0) {
        const int n4 = (int)(off / 4);
        idxcopy_kernel<<<(n4 + 255) / 256, 256>>>(index, out, n4);                // k5
    }
}

// round 17
// speedup vs baseline: 1.0641x; 1.0102x over previous
#include <cuda_runtime.h>
#include <cuda_fp16.h>
#include <cstdint>

// Problem constants
#define B_   4
#define N_   262144          // elements per batch (2^18)
#define F_   64
#define S_   1024            // NUM_SEG
#define OUT_ 64
#define CAP  512             // bin capacity (Poisson lambda=256, >15 sigma headroom)

// ---------------- device scratch ----------------
__device__ __align__(256) unsigned g_zeroblk[2 * B_ * S_ + B_ * 64];
#define CNT_ROW ((int*)g_zeroblk)
#define CNT_COL (((int*)g_zeroblk) + B_ * S_)
#define GSUM    ((float*)(g_zeroblk + 2 * B_ * S_))

__device__ __align__(256) int g_bins[2 * B_ * S_ * CAP];   // 16 MB

__device__ __align__(256) float g_M[4 * F_ * OUT_];        // M_self, M_row, M_col, M_glob
__device__ __align__(256) float g_bias_const[OUT_];
// fp16 paired tables: uint32[(b,s)][32], each = half2(out o, out o+32)
__device__ __align__(256) uint32_t g_rowvec[B_ * S_ * 32];
__device__ __align__(256) uint32_t g_colvec[B_ * S_ * 32];

// ---------------- helpers ----------------
__device__ __forceinline__ uint32_t smem_u32(const void* p) {
    uint32_t a;
    asm("{ .reg .u64 t; cvta.to.shared.u64 t, %1; cvt.u32.u64 %0, t; }" : "=r"(a) : "l"(p));
    return a;
}
__device__ __forceinline__ uint32_t f16pk(float lo_e, float hi_e) {   // lower half = lo_e
    const __half2 h = __floats2half2_rn(lo_e, hi_e);
    return *(const uint32_t*)&h;
}
__device__ __forceinline__ float2 f16up(uint32_t v) {
    const __half2 h = *(const __half2*)&v;
    return __half22float2(h);
}
__device__ __forceinline__ void ldsm_x4(uint32_t* r, uint32_t addr) {
    asm volatile("ldmatrix.sync.aligned.m8n8.x4.shared.b16 {%0,%1,%2,%3}, [%4];"
                 : "=r"(r[0]), "=r"(r[1]), "=r"(r[2]), "=r"(r[3]) : "r"(addr));
}
__device__ __forceinline__ void ldsm_x4t(uint32_t* r, uint32_t addr) {
    asm volatile("ldmatrix.sync.aligned.m8n8.x4.trans.shared.b16 {%0,%1,%2,%3}, [%4];"
                 : "=r"(r[0]), "=r"(r[1]), "=r"(r[2]), "=r"(r[3]) : "r"(addr));
}
__device__ __forceinline__ void mma16816(float* c, const uint32_t* a, uint32_t b0, uint32_t b1) {
    asm volatile("mma.sync.aligned.m16n8k16.row.col.f32.f16.f16.f32 "
                 "{%0,%1,%2,%3}, {%4,%5,%6,%7}, {%8,%9}, {%0,%1,%2,%3};"
                 : "+f"(c[0]), "+f"(c[1]), "+f"(c[2]), "+f"(c[3])
                 : "r"(a[0]), "r"(a[1]), "r"(a[2]), "r"(a[3]), "r"(b0), "r"(b1));
}

// ---------------- K0: fold weight matrices ----------------
__global__ void prep_kernel(const float* __restrict__ Wself, const float* __restrict__ Wrow,
                            const float* __restrict__ Wcol,  const float* __restrict__ Wglob,
                            const float* __restrict__ Wout,
                            const float* __restrict__ bself, const float* __restrict__ brow,
                            const float* __restrict__ bcol,  const float* __restrict__ bglob,
                            const float* __restrict__ bout) {
    const int stride = blockDim.x * gridDim.x;
    const int tid = blockIdx.x * blockDim.x + threadIdx.x;
    for (int job = tid; job < 4 * F_ * OUT_; job += stride) {
        const int m = job >> 12;
        const int r = job & 4095;
        const int f = r >> 6, o = r & 63;
        const float* W = (m == 0) ? Wself : (m == 1) ? Wrow : (m == 2) ? Wcol : Wglob;
        float acc = 0.f;
        #pragma unroll 16
        for (int j = 0; j < 64; ++j)
            acc += W[f * 64 + j] * Wout[(m * 64 + j) * OUT_ + o];
        g_M[job] = acc;
    }
    for (int o = tid; o < OUT_; o += stride) {
        float acc = bout[o];
        for (int j = 0; j < 64; ++j) {
            acc += bself[j] * Wout[j * OUT_ + o];
            acc += brow [j] * Wout[(64  + j) * OUT_ + o];
            acc += bcol [j] * Wout[(128 + j) * OUT_ + o];
            acc += bglob[j] * Wout[(192 + j) * OUT_ + o];
        }
        g_bias_const[o] = acc;
    }
}

// ---------------- K1: block-aggregated binning ----------------
__global__ void __launch_bounds__(256) bin_kernel(const int* __restrict__ index) {
    __shared__ int cnt[2048];
    __shared__ int basep[2048];
    const int tid = threadIdx.x;
    const int b = blockIdx.x >> 6;
    const long long ebase = (long long)blockIdx.x * 4096;

    #pragma unroll
    for (int i = 0; i < 8; ++i) cnt[tid + i * 256] = 0;
    __syncthreads();

    int2 p[16];
    int posr[16], posc[16];
    #pragma unroll
    for (int j = 0; j < 16; ++j) {
        p[j] = ((const int2*)index)[ebase + j * 256 + tid];
        posr[j] = atomicAdd(&cnt[p[j].x], 1);
        posc[j] = atomicAdd(&cnt[1024 + p[j].y], 1);
    }
    __syncthreads();

    for (int s = tid; s < 2048; s += 256) {
        const int c = cnt[s];
        if (c > 0) {
            int* ctr = (s < 1024) ? (CNT_ROW + (b << 10) + s)
                                  : (CNT_COL + (b << 10) + (s - 1024));
            basep[s] = atomicAdd(ctr, c);
        }
    }
    __syncthreads();

    #pragma unroll
    for (int j = 0; j < 16; ++j) {
        const int local = (int)((ebase + j * 256 + tid) & (N_ - 1));
        const int sr = basep[p[j].x] + posr[j];
        if (sr < CAP) g_bins[((b << 10) + p[j].x) * CAP + sr] = local;
        const int sc = basep[1024 + p[j].y] + posc[j];
        if (sc < CAP) g_bins[(B_ * S_ + (b << 10) + p[j].y) * CAP + sc] = local;
    }
}

// ---------------- K2: batch-phased per-segment reduce + fused GEMV ----------------
// 256 persistent CTAs = 2048 warps = exactly one batch's jobs (1024 segs x 2 sides).
// Each warp loops b=0..3 so the chip processes ~one batch (64MB) at a time:
// each element's two reads (row-side + col-side) land within L2 residency -> the
// second read is an L2 hit, halving reduce's DRAM traffic.
__global__ void __launch_bounds__(256) reduce_kernel(const float* __restrict__ value) {
    __shared__ float Ms[2 * 4096];
    const int tid = threadIdx.x;
    {
        const float4* src = (const float4*)(g_M + 4096);
        float4* dst = (float4*)Ms;
        #pragma unroll
        for (int i = 0; i < 8; ++i) dst[tid + i * 256] = src[tid + i * 256];
    }
    __syncthreads();

    const int warp = tid >> 5, lane = tid & 31;
    const int gw = blockIdx.x * 8 + warp;     // 0..2047
    const int side = gw >> 10;                 // 0=row 1=col
    const int s = gw & 1023;
    const float* M = Ms + side * 4096;

    for (int b = 0; b < B_; ++b) {
        const int bs = (b << 10) + s;
        const int cnt = (side ? CNT_COL : CNT_ROW)[bs];
        const int mn = min(cnt, CAP);
        const int* ids = g_bins + ((long long)side * B_ * S_ + bs) * CAP;
        const float* vb = value + ((long long)b << 24);

        float2 acc = make_float2(0.f, 0.f);
        int base = 0;
        int idv_next = (mn > 0) ? ids[lane] : 0;   // prefetch first batch's ids
        for (; base + 32 <= mn; base += 32) {
            const int idv = idv_next;
            if (base + 64 <= mn) idv_next = ids[base + 32 + lane];
            #pragma unroll
            for (int jj = 0; jj < 32; jj += 16) {
                float2 v[16];
                #pragma unroll
                for (int j = 0; j < 16; ++j) {
                    const int id = __shfl_sync(0xffffffff, idv, jj + j);
                    v[j] = *(const float2*)(vb + ((long long)id << 6) + (lane << 1));
                }
                #pragma unroll
                for (int j = 0; j < 16; ++j) { acc.x += v[j].x; acc.y += v[j].y; }
            }
        }
        {
            const int rem = mn - base;
            const int idv = (lane < rem) ? ((base > 0 || mn >= 32) ? ids[base + lane] : idv_next) : 0;
            for (int j = 0; j < rem; ++j) {
                const int id = __shfl_sync(0xffffffff, idv, j);
                const float2 v = *(const float2*)(vb + ((long long)id << 6) + (lane << 1));
                acc.x += v.x; acc.y += v.y;
            }
        }

        if (side == 0) {
            atomicAdd(GSUM + b * 64 + (lane << 1),     acc.x);
            atomicAdd(GSUM + b * 64 + (lane << 1) + 1, acc.y);
        }

        const float inv = 1.0f / ((float)cnt + 1e-9f);
        const float2 mean = make_float2(acc.x * inv, acc.y * inv);

        float r0 = 0.f, r1 = 0.f;
        #pragma unroll 8
        for (int j = 0; j < 32; ++j) {
            const float m0 = __shfl_sync(0xffffffff, mean.x, j);
            const float m1 = __shfl_sync(0xffffffff, mean.y, j);
            r0 += m0 * M[(2 * j) * 64 + lane]      + m1 * M[(2 * j + 1) * 64 + lane];
            r1 += m0 * M[(2 * j) * 64 + lane + 32] + m1 * M[(2 * j + 1) * 64 + lane + 32];
        }
        (side ? g_colvec : g_rowvec)[((long long)bs << 5) + lane] = f16pk(r0, r1);
    }
}

// ---------------- K3: mma.sync main — fp16 GEMM, R16 structure (unchanged) ----------------
#define SM_A      0                      // 8 strips x 2304 B
#define SM_B      18432                  // 9216 B (single fp16 image)
#define SM_BB     27648
#define SMEM_MMA  27904
#define ROWS_PER_WARP 128
#define GROUPS 8

__global__ void __launch_bounds__(256, 2) main_mma_kernel(const float* __restrict__ value,
                                                          const int* __restrict__ index,
                                                          float* __restrict__ out) {
    extern __shared__ char sm[];
    const uint32_t smb = smem_u32(sm);
    float* bbF = (float*)(sm + SM_BB);
    const int tid = threadIdx.x;
    const int lane = tid & 31, w = tid >> 5;
    const int b = blockIdx.x >> 8;    // 256 CTAs per batch

    // stage B (single fp16) directly from g_M into padded [k][72] smem rows
    #pragma unroll
    for (int i = 0; i < 8; ++i) {
        const int idx = i * 256 + tid;       // k*32 + p
        const int k = idx >> 5, p = idx & 31;
        const float x0 = g_M[k * 64 + 2 * p];
        const float x1 = g_M[k * 64 + 2 * p + 1];
        *(uint32_t*)(sm + SM_B + k * 144 + p * 4) = f16pk(x0, x1);
    }
    // per-batch bias
    if (tid < 64) {
        const float s = 1.0f / (float)N_;
        float acc = g_bias_const[tid];
        #pragma unroll 8
        for (int f = 0; f < 64; ++f)
            acc += (GSUM[(b << 6) + f] * s) * g_M[3 * 4096 + f * 64 + tid];
        bbF[tid] = acc;
    }
    __syncthreads();   // the ONLY block barrier

    const int c0 = (lane & 3) * 2;
    const uint32_t* rvbase = g_rowvec + ((long long)b << 15);
    const uint32_t* cvbase = g_colvec + ((long long)b << 15);

    // warp-private A strip (16 rows x 144 B)
    const uint32_t aS = smb + SM_A + w * 2304;

    const long long wbase = ((long long)blockIdx.x << 10) + (long long)w * ROWS_PER_WARP;

    // preload group 0
    float4 v[8];
    int2 pp;
    {
        const float4* Vg = (const float4*)(value + (wbase << 6));
        #pragma unroll
        for (int i = 0; i < 8; ++i) v[i] = Vg[i * 32 + lane];
        if (lane < 16) pp = ((const int2*)index)[wbase + lane];
    }

    for (int g = 0; g < GROUPS; ++g) {
        const long long gbase = wbase + (long long)g * 16;

        // convert staged group to fp16 in this warp's strip
        #pragma unroll
        for (int i = 0; i < 8; ++i) {
            const int idx = i * 32 + lane;       // float4 index: r*16 + q
            const int r = idx >> 4, q = idx & 15;
            const uint32_t h01 = f16pk(v[i].x, v[i].y);
            const uint32_t h23 = f16pk(v[i].z, v[i].w);
            *(uint2*)(sm + SM_A + w * 2304 + r * 144 + q * 8) = make_uint2(h01, h23);
        }
        __syncwarp();

        const int2 ppc = pp;   // current group's indices (lanes 0-15)

        // prefetch next group
        if (g + 1 < GROUPS) {
            const float4* Vg = (const float4*)(value + ((gbase + 16) << 6));
            #pragma unroll
            for (int i = 0; i < 8; ++i) v[i] = Vg[i * 32 + lane];
            if (lane < 16) pp = ((const int2*)index)[gbase + 16 + lane];
        }

        float acc[8][4];
        #pragma unroll
        for (int n = 0; n < 8; ++n)
            #pragma unroll
            for (int q = 0; q < 4; ++q) acc[n][q] = 0.f;

        #pragma unroll
        for (int ks = 0; ks < 4; ++ks) {
            uint32_t ah[4];
            const uint32_t aoff = (uint32_t)((lane & 15) * 144 +
                                             (ks * 16 + (lane >> 4) * 8) * 2);
            ldsm_x4(ah, aS + aoff);
            const uint32_t brow = (uint32_t)((ks * 16 + (lane & 15)) * 144 +
                                             ((lane >> 4) * 8) * 2);
            #pragma unroll
            for (int gg = 0; gg < 4; ++gg) {
                uint32_t bh[4];
                ldsm_x4t(bh, smb + SM_B + brow + gg * 32);
                mma16816(acc[2 * gg],     ah, bh[0], bh[1]);
                mma16816(acc[2 * gg + 1], ah, bh[2], bh[3]);
            }
        }

        // fragment-direct epilogue: thread owns rows (lane/4, lane/4+8),
        // cols c0+8j (+1, +32, +33); rv/cv read as 8B uint2 of half2 pairs.
        #pragma unroll
        for (int half = 0; half < 2; ++half) {
            const int rg = (lane >> 2) + half * 8;
            const int s = half * 2;
            const int i0 = __shfl_sync(0xffffffff, ppc.x, rg);
            const int i1 = __shfl_sync(0xffffffff, ppc.y, rg);
            const uint32_t* rv = rvbase + ((long long)i0 << 5);
            const uint32_t* cv = cvbase + ((long long)i1 << 5);
            float* op = out + ((gbase + rg) << 6);
            #pragma unroll
            for (int j = 0; j < 4; ++j) {
                const int c = c0 + 8 * j;
                const uint2 rvu = *(const uint2*)(rv + c);
                const uint2 cvu = *(const uint2*)(cv + c);
                const float2 rv0 = f16up(rvu.x), rv1 = f16up(rvu.y);
                const float2 cv0 = f16up(cvu.x), cv1 = f16up(cvu.y);
                float x0 = acc[j][s]     + rv0.x + cv0.x + bbF[c];
                float x1 = acc[j][s + 1] + rv1.x + cv1.x + bbF[c + 1];
                float y0 = acc[j + 4][s]     + rv0.y + cv0.y + bbF[c + 32];
                float y1 = acc[j + 4][s + 1] + rv1.y + cv1.y + bbF[c + 33];
                x0 = fmaxf(x0, 0.01f * x0);
                x1 = fmaxf(x1, 0.01f * x1);
                y0 = fmaxf(y0, 0.01f * y0);
                y1 = fmaxf(y1, 0.01f * y1);
                *(float2*)(op + c)      = make_float2(x0, x1);
                *(float2*)(op + c + 32) = make_float2(y0, y1);
            }
        }
        __syncwarp();   // strip reuse safe for next group
    }
}

// ---------------- index pass-through ----------------
__global__ void idxcopy_kernel(const int* __restrict__ idx, float* __restrict__ out, int n4) {
    const int i = blockIdx.x * blockDim.x + threadIdx.x;
    if (i < n4) {
        const int4 v = ((const int4*)idx)[i];
        ((float4*)out)[i] = make_float4((float)v.x, (float)v.y, (float)v.z, (float)v.w);
    }
}

// ---------------- launch ----------------
extern "C" void kernel_launch(void* const* d_in, const int* in_sizes, int n_in,
                              void* d_out, int out_size) {
    const int*   index = (const int*)d_in[0];
    const float* value = (const float*)d_in[1];
    const float* Wself = (const float*)d_in[2];
    const float* bself = (const float*)d_in[3];
    const float* Wrow  = (const float*)d_in[4];
    const float* brow  = (const float*)d_in[5];
    const float* Wcol  = (const float*)d_in[6];
    const float* bcol  = (const float*)d_in[7];
    const float* Wglob = (const float*)d_in[8];
    const float* bglob = (const float*)d_in[9];
    const float* Wout  = (const float*)d_in[10];
    const float* bout  = (const float*)d_in[11];
    float* out = (float*)d_out;

    const long long main_elems = (long long)B_ * N_ * OUT_;
    const long long off = (long long)out_size - main_elems;
    float* out_main = (off > 0) ? (out + off) : out;

    void* zp = nullptr;
    cudaGetSymbolAddress(&zp, g_zeroblk);
    cudaMemsetAsync(zp, 0, sizeof(g_zeroblk), 0);

    cudaFuncSetAttribute(main_mma_kernel, cudaFuncAttributeMaxDynamicSharedMemorySize, SMEM_MMA);

    prep_kernel<<<64, 256>>>(Wself, Wrow, Wcol, Wglob, Wout,
                             bself, brow, bcol, bglob, bout);                     // k1
    bin_kernel<<<(B_ * N_) / 4096, 256>>>(index);                                 // k2
    if (off > 0) {
        const int n4 = (int)(off / 4);
        idxcopy_kernel<<<(n4 + 255) / 256, 256>>>(index, out, n4);                // k3
    }
    reduce_kernel<<<256, 256>>>(value);                                           // k4 (profiled)
    main_mma_kernel<<<1024, 256, SMEM_MMA>>>(value, index, out_main);             // k5
}